// round 4
// baseline (speedup 1.0000x reference)
#include <cuda_runtime.h>
#include <cstdint>

#define NCC   100000   // n_coarse
#define NFF   400000   // n_fine
#define CDIM  64
#define EPMAX 1200000
#define ECMAX 1600000
#define EUMAX 1200000

typedef unsigned long long u64;

// ---------------- scratch ----------------
__device__ float g_xc[(size_t)NCC * CDIM];
__device__ float g_t [(size_t)NCC * CDIM];
__device__ float g_h [(size_t)NCC * CDIM];

// CSR build scratch
__device__ int  g_pool_cnt[NCC + 1];
__device__ int  g_pool_off[NCC + 1];
__device__ int  g_pool_cur[NCC];
__device__ int2 g_pool_edges[EPMAX];

__device__ int  g_conv_cnt[NCC + 1];
__device__ int  g_conv_off[NCC + 1];
__device__ int  g_conv_cur[NCC];
__device__ int2 g_conv_edges[ECMAX];

__device__ int  g_unp_cnt[NFF + 1];
__device__ int  g_unp_off[NFF + 1];
__device__ int  g_unp_cur[NFF];
__device__ int2 g_unp_edges[EUMAX];

__device__ int  g_bsum[3 * 512];

// ---------------- helpers ----------------
__device__ __forceinline__ u64 pack2(float x) {
    u64 r;
    asm("mov.b64 %0, {%1, %1};" : "=l"(r) : "f"(x));
    return r;
}
__device__ __forceinline__ void fma2(u64& d, u64 a, u64 b) {
    asm("fma.rn.f32x2 %0, %1, %2, %0;" : "+l"(d) : "l"(a), "l"(b));
}

// ---------------- small utility kernels ----------------
__global__ void zero_int(int* __restrict__ p, int n) {
    int i = blockIdx.x * blockDim.x + threadIdx.x;
    if (i < n) p[i] = 0;
}

__global__ void hist_kernel(const int* __restrict__ dst, int* __restrict__ cnt, int E) {
    int i = blockIdx.x * blockDim.x + threadIdx.x;
    if (i < E) atomicAdd(&cnt[dst[i]], 1);
}

__global__ void scan_block(const int* __restrict__ cnt, int* __restrict__ off,
                           int* __restrict__ bsum, int n) {
    __shared__ int sh[1024];
    int tid = threadIdx.x;
    int i = blockIdx.x * 1024 + tid;
    int v = (i < n) ? cnt[i] : 0;
    sh[tid] = v;
    __syncthreads();
#pragma unroll
    for (int d = 1; d < 1024; d <<= 1) {
        int t = (tid >= d) ? sh[tid - d] : 0;
        __syncthreads();
        sh[tid] += t;
        __syncthreads();
    }
    if (i < n) off[i] = sh[tid] - v;
    if (tid == 1023) bsum[blockIdx.x] = sh[1023];
}

__global__ void scan_aux(int* __restrict__ bsum, int nb) {
    __shared__ int sh[1024];
    int tid = threadIdx.x;
    int v = (tid < nb) ? bsum[tid] : 0;
    sh[tid] = v;
    __syncthreads();
#pragma unroll
    for (int d = 1; d < 1024; d <<= 1) {
        int t = (tid >= d) ? sh[tid - d] : 0;
        __syncthreads();
        sh[tid] += t;
        __syncthreads();
    }
    if (tid < nb) bsum[tid] = sh[tid] - v;
}

__global__ void scan_add(int* __restrict__ off, const int* __restrict__ bsum,
                         int* __restrict__ cursor, int n) {
    int i = blockIdx.x * blockDim.x + threadIdx.x;
    if (i < n) {
        int o = off[i] + bsum[i >> 10];
        off[i] = o;
        if (i < n - 1) cursor[i] = o;
    }
}

__global__ void permute_kernel(const int* __restrict__ src, const int* __restrict__ dst,
                               const float* __restrict__ attr, int* __restrict__ cursor,
                               int2* __restrict__ edges, int E) {
    int i = blockIdx.x * blockDim.x + threadIdx.x;
    if (i < E) {
        int p = atomicAdd(&cursor[dst[i]], 1);
        edges[p] = make_int2(src[i], __float_as_int(attr[i]));
    }
}

// ---------------- CSR gather: 8 threads/node, 2x float4 per thread ----------------
template <bool INIT_FROM_OUT>
__global__ void __launch_bounds__(256) gather_kernel(
    const float* __restrict__ feat,
    const int2*  __restrict__ edges,
    const int*   __restrict__ off,
    float*       __restrict__ outp,
    int n)
{
    int idx = blockIdx.x * blockDim.x + threadIdx.x;
    int node = idx >> 3;
    if (node >= n) return;
    int q = (idx & 7) << 3;           // 8 floats per thread

    int e0 = __ldg(off + node);
    int e1 = __ldg(off + node + 1);

    float* orow = outp + (size_t)node * CDIM + q;
    float4 acc0, acc1;
    if (INIT_FROM_OUT) {
        acc0 = *reinterpret_cast<const float4*>(orow);
        acc1 = *reinterpret_cast<const float4*>(orow + 4);
    } else {
        acc0 = make_float4(0.f, 0.f, 0.f, 0.f);
        acc1 = acc0;
    }

#pragma unroll 2
    for (int e = e0; e < e1; e++) {
        int2 ed = __ldg(edges + e);
        float w = __int_as_float(ed.y);
        const float4* p = reinterpret_cast<const float4*>(feat + (size_t)ed.x * CDIM + q);
        float4 v0 = __ldg(p);
        float4 v1 = __ldg(p + 1);
        acc0.x = fmaf(w, v0.x, acc0.x);
        acc0.y = fmaf(w, v0.y, acc0.y);
        acc0.z = fmaf(w, v0.z, acc0.z);
        acc0.w = fmaf(w, v0.w, acc0.w);
        acc1.x = fmaf(w, v1.x, acc1.x);
        acc1.y = fmaf(w, v1.y, acc1.y);
        acc1.z = fmaf(w, v1.z, acc1.z);
        acc1.w = fmaf(w, v1.w, acc1.w);
    }
    *reinterpret_cast<float4*>(orow)     = acc0;
    *reinterpret_cast<float4*>(orow + 4) = acc1;
}

// ---------------- fused dual GEMM with 4-row register blocking ----------------
#define ROWS_PER_BLK 128
#define SA_STRIDE    68

__global__ void __launch_bounds__(256, 2) dual_gemm(
    const float* __restrict__ A,
    const float* __restrict__ Wn,
    const float* __restrict__ Wr,
    const float* __restrict__ bias,
    float* __restrict__ T,
    float* __restrict__ H,
    int N)
{
    __shared__ float sWn[CDIM * CDIM];
    __shared__ float sWr[CDIM * CDIM];
    __shared__ float sA[ROWS_PER_BLK * SA_STRIDE];

    const int t = threadIdx.x;

    {
        const float4* Wn4 = reinterpret_cast<const float4*>(Wn);
        const float4* Wr4 = reinterpret_cast<const float4*>(Wr);
        float4* sWn4 = reinterpret_cast<float4*>(sWn);
        float4* sWr4 = reinterpret_cast<float4*>(sWr);
#pragma unroll
        for (int i = 0; i < 4; i++) {
            sWn4[t + 256 * i] = Wn4[t + 256 * i];
            sWr4[t + 256 * i] = Wr4[t + 256 * i];
        }
    }

    const int rowBase = blockIdx.x * ROWS_PER_BLK;
#pragma unroll
    for (int i = 0; i < 8; i++) {
        int idx = t + 256 * i;
        int row = idx >> 4;
        int kc  = (idx & 15) * 4;
        float4 a;
        if (rowBase + row < N)
            a = *reinterpret_cast<const float4*>(A + (size_t)(rowBase + row) * CDIM + kc);
        else
            a = make_float4(0.f, 0.f, 0.f, 0.f);
        *reinterpret_cast<float4*>(sA + row * SA_STRIDE + kc) = a;
    }
    __syncthreads();

    const int c0 = (t & 7) * 8;
    const int r0 = (t >> 3) * 4;

    u64 accT[4][4], accR[4][4];
    {
        const u64* b2 = reinterpret_cast<const u64*>(bias + c0);
        u64 bv[4];
#pragma unroll
        for (int j = 0; j < 4; j++) bv[j] = b2[j];
#pragma unroll
        for (int r = 0; r < 4; r++)
#pragma unroll
            for (int j = 0; j < 4; j++) { accT[r][j] = 0ull; accR[r][j] = bv[j]; }
    }

#pragma unroll 8
    for (int k = 0; k < CDIM; k++) {
        u64 a0 = pack2(sA[(r0 + 0) * SA_STRIDE + k]);
        u64 a1 = pack2(sA[(r0 + 1) * SA_STRIDE + k]);
        u64 a2 = pack2(sA[(r0 + 2) * SA_STRIDE + k]);
        u64 a3 = pack2(sA[(r0 + 3) * SA_STRIDE + k]);

        // weight reads as 16B vectors (LDS.128) — halves MIO instruction count
        ulonglong2 nA = *reinterpret_cast<const ulonglong2*>(sWn + k * CDIM + c0);
        ulonglong2 nB = *reinterpret_cast<const ulonglong2*>(sWn + k * CDIM + c0 + 4);
        ulonglong2 qA = *reinterpret_cast<const ulonglong2*>(sWr + k * CDIM + c0);
        ulonglong2 qB = *reinterpret_cast<const ulonglong2*>(sWr + k * CDIM + c0 + 4);
        u64 n0 = nA.x, n1 = nA.y, n2 = nB.x, n3 = nB.y;
        u64 q0 = qA.x, q1 = qA.y, q2 = qB.x, q3 = qB.y;

        fma2(accT[0][0], a0, n0); fma2(accT[0][1], a0, n1); fma2(accT[0][2], a0, n2); fma2(accT[0][3], a0, n3);
        fma2(accT[1][0], a1, n0); fma2(accT[1][1], a1, n1); fma2(accT[1][2], a1, n2); fma2(accT[1][3], a1, n3);
        fma2(accT[2][0], a2, n0); fma2(accT[2][1], a2, n1); fma2(accT[2][2], a2, n2); fma2(accT[2][3], a2, n3);
        fma2(accT[3][0], a3, n0); fma2(accT[3][1], a3, n1); fma2(accT[3][2], a3, n2); fma2(accT[3][3], a3, n3);

        fma2(accR[0][0], a0, q0); fma2(accR[0][1], a0, q1); fma2(accR[0][2], a0, q2); fma2(accR[0][3], a0, q3);
        fma2(accR[1][0], a1, q0); fma2(accR[1][1], a1, q1); fma2(accR[1][2], a1, q2); fma2(accR[1][3], a1, q3);
        fma2(accR[2][0], a2, q0); fma2(accR[2][1], a2, q1); fma2(accR[2][2], a2, q2); fma2(accR[2][3], a2, q3);
        fma2(accR[3][0], a3, q0); fma2(accR[3][1], a3, q1); fma2(accR[3][2], a3, q2); fma2(accR[3][3], a3, q3);
    }

#pragma unroll
    for (int r = 0; r < 4; r++) {
        const int grow = rowBase + r0 + r;
        if (grow < N) {
            ulonglong2 t0, t1, h0, h1;
            t0.x = accT[r][0]; t0.y = accT[r][1]; t1.x = accT[r][2]; t1.y = accT[r][3];
            h0.x = accR[r][0]; h0.y = accR[r][1]; h1.x = accR[r][2]; h1.y = accR[r][3];
            *reinterpret_cast<ulonglong2*>(T + (size_t)grow * CDIM + c0)     = t0;
            *reinterpret_cast<ulonglong2*>(T + (size_t)grow * CDIM + c0 + 4) = t1;
            *reinterpret_cast<ulonglong2*>(H + (size_t)grow * CDIM + c0)     = h0;
            *reinterpret_cast<ulonglong2*>(H + (size_t)grow * CDIM + c0 + 4) = h1;
        }
    }
}

// ---------------- host-side CSR build helper (on a given stream) ----------------
static void build_csr(const int* src, const int* dst, const float* attr, int E,
                      int* cnt, int* off, int* cur, int2* edges, int* bsum, int nNodes,
                      cudaStream_t s)
{
    const int n1 = nNodes + 1;
    zero_int<<<(n1 + 255) / 256, 256, 0, s>>>(cnt, n1);
    hist_kernel<<<(E + 255) / 256, 256, 0, s>>>(dst, cnt, E);
    int nb = (n1 + 1023) / 1024;
    scan_block<<<nb, 1024, 0, s>>>(cnt, off, bsum, n1);
    scan_aux<<<1, 1024, 0, s>>>(bsum, nb);
    scan_add<<<(n1 + 255) / 256, 256, 0, s>>>(off, bsum, cur, n1);
    permute_kernel<<<(E + 255) / 256, 256, 0, s>>>(src, dst, attr, cur, edges, E);
}

// ---------------- launch ----------------
extern "C" void kernel_launch(void* const* d_in, const int* in_sizes, int n_in,
                              void* d_out, int out_size)
{
    const float* x    = (const float*)d_in[0];
    const float* W1r  = (const float*)d_in[1];
    const float* W1n  = (const float*)d_in[2];
    const float* b1   = (const float*)d_in[3];
    const float* W2r  = (const float*)d_in[4];
    const float* W2n  = (const float*)d_in[5];
    const float* b2   = (const float*)d_in[6];
    const int*   psrc = (const int*)d_in[7];
    const int*   pdst = (const int*)d_in[8];
    const float* patt = (const float*)d_in[9];
    const int*   csrc = (const int*)d_in[10];
    const int*   cdst = (const int*)d_in[11];
    const float* catt = (const float*)d_in[12];
    const int*   usrc = (const int*)d_in[13];
    const int*   udst = (const int*)d_in[14];
    const float* uatt = (const float*)d_in[15];

    const int Ep = in_sizes[7];
    const int Ec = in_sizes[10];
    const int Eu = in_sizes[13];

    float* out = (float*)d_out;

    float *xc, *tb, *hb;
    cudaGetSymbolAddress((void**)&xc, g_xc);
    cudaGetSymbolAddress((void**)&tb, g_t);
    cudaGetSymbolAddress((void**)&hb, g_h);

    int *pcnt, *poff, *pcur, *ccnt, *coff, *ccur, *ucnt, *uoff, *ucur, *bsum;
    int2 *pedg, *cedg, *uedg;
    cudaGetSymbolAddress((void**)&pcnt, g_pool_cnt);
    cudaGetSymbolAddress((void**)&poff, g_pool_off);
    cudaGetSymbolAddress((void**)&pcur, g_pool_cur);
    cudaGetSymbolAddress((void**)&pedg, g_pool_edges);
    cudaGetSymbolAddress((void**)&ccnt, g_conv_cnt);
    cudaGetSymbolAddress((void**)&coff, g_conv_off);
    cudaGetSymbolAddress((void**)&ccur, g_conv_cur);
    cudaGetSymbolAddress((void**)&cedg, g_conv_edges);
    cudaGetSymbolAddress((void**)&ucnt, g_unp_cnt);
    cudaGetSymbolAddress((void**)&uoff, g_unp_off);
    cudaGetSymbolAddress((void**)&ucur, g_unp_cur);
    cudaGetSymbolAddress((void**)&uedg, g_unp_edges);
    cudaGetSymbolAddress((void**)&bsum, g_bsum);

    // one-time host resources (streams + events) for fork/join inside capture
    static cudaStream_t sB = nullptr, sC = nullptr;
    static cudaEvent_t ev0 = nullptr, evB = nullptr, evC = nullptr;
    if (sB == nullptr) {
        cudaStreamCreateWithFlags(&sB, cudaStreamNonBlocking);
        cudaStreamCreateWithFlags(&sC, cudaStreamNonBlocking);
        cudaEventCreateWithFlags(&ev0, cudaEventDisableTiming);
        cudaEventCreateWithFlags(&evB, cudaEventDisableTiming);
        cudaEventCreateWithFlags(&evC, cudaEventDisableTiming);
    }

    // fork: conv CSR on sB, unpool CSR on sC (needed later; off critical path)
    cudaEventRecord(ev0, 0);
    cudaStreamWaitEvent(sB, ev0, 0);
    cudaStreamWaitEvent(sC, ev0, 0);
    build_csr(csrc, cdst, catt, Ec, ccnt, coff, ccur, cedg, bsum + 512,  NCC, sB);
    cudaEventRecord(evB, sB);
    build_csr(usrc, udst, uatt, Eu, ucnt, uoff, ucur, uedg, bsum + 1024, NFF, sC);
    cudaEventRecord(evC, sC);

    // critical path on stream 0
    build_csr(psrc, pdst, patt, Ep, pcnt, poff, pcur, pedg, bsum, NCC, 0);

    const int gthreadsC = NCC * 8;
    const int gthreadsF = NFF * 8;

    // pool: xc = gather(x)
    gather_kernel<false><<<(gthreadsC + 255) / 256, 256>>>(x, pedg, poff, xc, NCC);

    // layer 1
    dual_gemm<<<(NCC + ROWS_PER_BLK - 1) / ROWS_PER_BLK, 256>>>(xc, W1n, W1r, b1, tb, hb, NCC);
    cudaStreamWaitEvent(0, evB, 0);
    gather_kernel<true><<<(gthreadsC + 255) / 256, 256>>>(tb, cedg, coff, hb, NCC);

    // layer 2
    dual_gemm<<<(NCC + ROWS_PER_BLK - 1) / ROWS_PER_BLK, 256>>>(hb, W2n, W2r, b2, tb, xc, NCC);
    gather_kernel<true><<<(gthreadsC + 255) / 256, 256>>>(tb, cedg, coff, xc, NCC);

    // unpool
    cudaStreamWaitEvent(0, evC, 0);
    gather_kernel<false><<<(gthreadsF + 255) / 256, 256>>>(xc, uedg, uoff, out, NFF);
}

// round 5
// speedup vs baseline: 1.0371x; 1.0371x over previous
#include <cuda_runtime.h>
#include <cstdint>

#define NCC   100000   // n_coarse
#define NFF   400000   // n_fine
#define CDIM  64
#define EPMAX 1200000
#define ECMAX 1600000
#define EUMAX 1200000

typedef unsigned long long u64;

// ---------------- scratch ----------------
__device__ float g_xc[(size_t)NCC * CDIM];
__device__ float g_t [(size_t)NCC * CDIM];
__device__ float g_h [(size_t)NCC * CDIM];

// CSR build scratch
__device__ int  g_pool_cnt[NCC + 4];
__device__ int  g_pool_off[NCC + 4];
__device__ int  g_pool_cur[NCC];
__device__ int2 g_pool_edges[EPMAX];

__device__ int  g_conv_cnt[NCC + 4];
__device__ int  g_conv_off[NCC + 4];
__device__ int  g_conv_cur[NCC];
__device__ int2 g_conv_edges[ECMAX];

__device__ int  g_unp_cnt[NFF + 4];
__device__ int  g_unp_off[NFF + 4];
__device__ int  g_unp_cur[NFF];
__device__ int2 g_unp_edges[EUMAX];

__device__ int  g_bsum[3 * 512];

// ---------------- helpers ----------------
__device__ __forceinline__ u64 pack2(float x) {
    u64 r;
    asm("mov.b64 %0, {%1, %1};" : "=l"(r) : "f"(x));
    return r;
}
__device__ __forceinline__ void fma2(u64& d, u64 a, u64 b) {
    asm("fma.rn.f32x2 %0, %1, %2, %0;" : "+l"(d) : "l"(a), "l"(b));
}

// ---------------- small utility kernels (int4-vectorized) ----------------
__global__ void zero_int(int* __restrict__ p, int n) {
    int i = (blockIdx.x * blockDim.x + threadIdx.x) * 4;
    if (i + 3 < n) {
        *reinterpret_cast<int4*>(p + i) = make_int4(0, 0, 0, 0);
    } else {
        for (int j = i; j < n && j < i + 4; j++) p[j] = 0;
    }
}

__global__ void hist_kernel(const int* __restrict__ dst, int* __restrict__ cnt, int E) {
    int i = (blockIdx.x * blockDim.x + threadIdx.x) * 4;
    if (i + 3 < E) {
        int4 d = *reinterpret_cast<const int4*>(dst + i);
        atomicAdd(&cnt[d.x], 1);
        atomicAdd(&cnt[d.y], 1);
        atomicAdd(&cnt[d.z], 1);
        atomicAdd(&cnt[d.w], 1);
    } else {
        for (int j = i; j < E && j < i + 4; j++) atomicAdd(&cnt[dst[j]], 1);
    }
}

// ---- scan level 1: per-block (1024 elems) reduction via shfl ----
__global__ void __launch_bounds__(256) reduce_blk(
    const int* __restrict__ cnt, int* __restrict__ bsum, int n)
{
    __shared__ int ws[8];
    int tid = threadIdx.x;
    int base = blockIdx.x * 1024 + tid * 4;
    int s = 0;
    if (base + 3 < n) {
        int4 v = *reinterpret_cast<const int4*>(cnt + base);
        s = v.x + v.y + v.z + v.w;
    } else {
        for (int j = base; j < n && j < base + 4; j++) s += cnt[j];
    }
#pragma unroll
    for (int o = 16; o; o >>= 1) s += __shfl_down_sync(0xffffffffu, s, o);
    if ((tid & 31) == 0) ws[tid >> 5] = s;
    __syncthreads();
    if (tid < 8) {
        int t = ws[tid];
#pragma unroll
        for (int o = 4; o; o >>= 1) t += __shfl_down_sync(0xffu, t, o);
        if (tid == 0) bsum[blockIdx.x] = t;
    }
}

// ---- scan level 2: exclusive scan of nb (<=512) partials, one block, shfl ----
__global__ void __launch_bounds__(512) scan_partials(int* __restrict__ bsum, int nb) {
    __shared__ int ws[16];
    int tid = threadIdx.x, lane = tid & 31, wid = tid >> 5;
    int v = (tid < nb) ? bsum[tid] : 0;
    int p = v;
#pragma unroll
    for (int o = 1; o < 32; o <<= 1) {
        int t = __shfl_up_sync(0xffffffffu, p, o);
        if (lane >= o) p += t;
    }
    if (lane == 31) ws[wid] = p;
    __syncthreads();
    if (tid < 16) {
        int t = ws[tid];
        int q = t;
#pragma unroll
        for (int o = 1; o < 16; o <<= 1) {
            int u = __shfl_up_sync(0xffffu, q, o);
            if (tid >= o) q += u;
        }
        ws[tid] = q - t;   // exclusive
    }
    __syncthreads();
    if (tid < nb) bsum[tid] = p - v + ws[wid];
}

// ---- scan level 3: in-block exclusive scan + block offset; writes off & cursor ----
__global__ void __launch_bounds__(256) scan_final(
    const int* __restrict__ cnt, const int* __restrict__ bsum,
    int* __restrict__ off, int* __restrict__ cursor, int n)
{
    __shared__ int ws[8];
    int tid = threadIdx.x, lane = tid & 31, wid = tid >> 5;
    int base = blockIdx.x * 1024 + tid * 4;
    int v0 = 0, v1 = 0, v2 = 0, v3 = 0;
    if (base + 3 < n) {
        int4 v = *reinterpret_cast<const int4*>(cnt + base);
        v0 = v.x; v1 = v.y; v2 = v.z; v3 = v.w;
    } else {
        if (base + 0 < n) v0 = cnt[base + 0];
        if (base + 1 < n) v1 = cnt[base + 1];
        if (base + 2 < n) v2 = cnt[base + 2];
        if (base + 3 < n) v3 = cnt[base + 3];
    }
    int s = v0 + v1 + v2 + v3;
    int p = s;
#pragma unroll
    for (int o = 1; o < 32; o <<= 1) {
        int t = __shfl_up_sync(0xffffffffu, p, o);
        if (lane >= o) p += t;
    }
    if (lane == 31) ws[wid] = p;
    __syncthreads();
    if (tid < 8) {
        int t = ws[tid];
        int q = t;
#pragma unroll
        for (int o = 1; o < 8; o <<= 1) {
            int u = __shfl_up_sync(0xffu, q, o);
            if (tid >= o) q += u;
        }
        ws[tid] = q - t;   // exclusive
    }
    __syncthreads();
    int excl = __ldg(bsum + blockIdx.x) + ws[wid] + (p - s);

    int o0 = excl, o1 = excl + v0, o2 = o1 + v1, o3 = o2 + v2;
    if (base + 3 < n) {
        *reinterpret_cast<int4*>(off + base) = make_int4(o0, o1, o2, o3);
    } else {
        if (base + 0 < n) off[base + 0] = o0;
        if (base + 1 < n) off[base + 1] = o1;
        if (base + 2 < n) off[base + 2] = o2;
        if (base + 3 < n) off[base + 3] = o3;
    }
    // cursor covers nodes only (n-1 entries)
    if (base + 0 < n - 1) cursor[base + 0] = o0;
    if (base + 1 < n - 1) cursor[base + 1] = o1;
    if (base + 2 < n - 1) cursor[base + 2] = o2;
    if (base + 3 < n - 1) cursor[base + 3] = o3;
}

__global__ void permute_kernel(const int* __restrict__ src, const int* __restrict__ dst,
                               const float* __restrict__ attr, int* __restrict__ cursor,
                               int2* __restrict__ edges, int E) {
    int i = (blockIdx.x * blockDim.x + threadIdx.x) * 4;
    if (i + 3 < E) {
        int4   sv = *reinterpret_cast<const int4*>(src + i);
        int4   dv = *reinterpret_cast<const int4*>(dst + i);
        float4 av = *reinterpret_cast<const float4*>(attr + i);
        int p0 = atomicAdd(&cursor[dv.x], 1);
        int p1 = atomicAdd(&cursor[dv.y], 1);
        int p2 = atomicAdd(&cursor[dv.z], 1);
        int p3 = atomicAdd(&cursor[dv.w], 1);
        edges[p0] = make_int2(sv.x, __float_as_int(av.x));
        edges[p1] = make_int2(sv.y, __float_as_int(av.y));
        edges[p2] = make_int2(sv.z, __float_as_int(av.z));
        edges[p3] = make_int2(sv.w, __float_as_int(av.w));
    } else {
        for (int j = i; j < E && j < i + 4; j++) {
            int p = atomicAdd(&cursor[dst[j]], 1);
            edges[p] = make_int2(src[j], __float_as_int(attr[j]));
        }
    }
}

// ---------------- CSR gather: 8 threads/node, 2x float4 per thread ----------------
template <bool INIT_FROM_OUT>
__global__ void __launch_bounds__(256) gather_kernel(
    const float* __restrict__ feat,
    const int2*  __restrict__ edges,
    const int*   __restrict__ off,
    float*       __restrict__ outp,
    int n)
{
    int idx = blockIdx.x * blockDim.x + threadIdx.x;
    int node = idx >> 3;
    if (node >= n) return;
    int q = (idx & 7) << 3;

    int e0 = __ldg(off + node);
    int e1 = __ldg(off + node + 1);

    float* orow = outp + (size_t)node * CDIM + q;
    float4 acc0, acc1;
    if (INIT_FROM_OUT) {
        acc0 = *reinterpret_cast<const float4*>(orow);
        acc1 = *reinterpret_cast<const float4*>(orow + 4);
    } else {
        acc0 = make_float4(0.f, 0.f, 0.f, 0.f);
        acc1 = acc0;
    }

#pragma unroll 2
    for (int e = e0; e < e1; e++) {
        int2 ed = __ldg(edges + e);
        float w = __int_as_float(ed.y);
        const float4* p = reinterpret_cast<const float4*>(feat + (size_t)ed.x * CDIM + q);
        float4 v0 = __ldg(p);
        float4 v1 = __ldg(p + 1);
        acc0.x = fmaf(w, v0.x, acc0.x);
        acc0.y = fmaf(w, v0.y, acc0.y);
        acc0.z = fmaf(w, v0.z, acc0.z);
        acc0.w = fmaf(w, v0.w, acc0.w);
        acc1.x = fmaf(w, v1.x, acc1.x);
        acc1.y = fmaf(w, v1.y, acc1.y);
        acc1.z = fmaf(w, v1.z, acc1.z);
        acc1.w = fmaf(w, v1.w, acc1.w);
    }
    *reinterpret_cast<float4*>(orow)     = acc0;
    *reinterpret_cast<float4*>(orow + 4) = acc1;
}

// ---------------- fused dual GEMM with 4-row register blocking ----------------
#define ROWS_PER_BLK 128
#define SA_STRIDE    68

__global__ void __launch_bounds__(256, 2) dual_gemm(
    const float* __restrict__ A,
    const float* __restrict__ Wn,
    const float* __restrict__ Wr,
    const float* __restrict__ bias,
    float* __restrict__ T,
    float* __restrict__ H,
    int N)
{
    __shared__ float sWn[CDIM * CDIM];
    __shared__ float sWr[CDIM * CDIM];
    __shared__ float sA[ROWS_PER_BLK * SA_STRIDE];

    const int t = threadIdx.x;

    {
        const float4* Wn4 = reinterpret_cast<const float4*>(Wn);
        const float4* Wr4 = reinterpret_cast<const float4*>(Wr);
        float4* sWn4 = reinterpret_cast<float4*>(sWn);
        float4* sWr4 = reinterpret_cast<float4*>(sWr);
#pragma unroll
        for (int i = 0; i < 4; i++) {
            sWn4[t + 256 * i] = Wn4[t + 256 * i];
            sWr4[t + 256 * i] = Wr4[t + 256 * i];
        }
    }

    const int rowBase = blockIdx.x * ROWS_PER_BLK;
#pragma unroll
    for (int i = 0; i < 8; i++) {
        int idx = t + 256 * i;
        int row = idx >> 4;
        int kc  = (idx & 15) * 4;
        float4 a;
        if (rowBase + row < N)
            a = *reinterpret_cast<const float4*>(A + (size_t)(rowBase + row) * CDIM + kc);
        else
            a = make_float4(0.f, 0.f, 0.f, 0.f);
        *reinterpret_cast<float4*>(sA + row * SA_STRIDE + kc) = a;
    }
    __syncthreads();

    const int c0 = (t & 7) * 8;
    const int r0 = (t >> 3) * 4;

    u64 accT[4][4], accR[4][4];
    {
        const u64* b2 = reinterpret_cast<const u64*>(bias + c0);
        u64 bv[4];
#pragma unroll
        for (int j = 0; j < 4; j++) bv[j] = b2[j];
#pragma unroll
        for (int r = 0; r < 4; r++)
#pragma unroll
            for (int j = 0; j < 4; j++) { accT[r][j] = 0ull; accR[r][j] = bv[j]; }
    }

    const float4* sA4_0 = reinterpret_cast<const float4*>(sA + (r0 + 0) * SA_STRIDE);
    const float4* sA4_1 = reinterpret_cast<const float4*>(sA + (r0 + 1) * SA_STRIDE);
    const float4* sA4_2 = reinterpret_cast<const float4*>(sA + (r0 + 2) * SA_STRIDE);
    const float4* sA4_3 = reinterpret_cast<const float4*>(sA + (r0 + 3) * SA_STRIDE);

#pragma unroll 2
    for (int k4 = 0; k4 < 16; k4++) {
        // stage 4 rows x 4 k-values of A with LDS.128 (1.25 LDS/k vs 8/k scalar)
        float4 a40 = sA4_0[k4];
        float4 a41 = sA4_1[k4];
        float4 a42 = sA4_2[k4];
        float4 a43 = sA4_3[k4];
#pragma unroll
        for (int j = 0; j < 4; j++) {
            const int k = k4 * 4 + j;
            u64 a0 = pack2(j == 0 ? a40.x : j == 1 ? a40.y : j == 2 ? a40.z : a40.w);
            u64 a1 = pack2(j == 0 ? a41.x : j == 1 ? a41.y : j == 2 ? a41.z : a41.w);
            u64 a2 = pack2(j == 0 ? a42.x : j == 1 ? a42.y : j == 2 ? a42.z : a42.w);
            u64 a3 = pack2(j == 0 ? a43.x : j == 1 ? a43.y : j == 2 ? a43.z : a43.w);

            ulonglong2 nA = *reinterpret_cast<const ulonglong2*>(sWn + k * CDIM + c0);
            ulonglong2 nB = *reinterpret_cast<const ulonglong2*>(sWn + k * CDIM + c0 + 4);
            ulonglong2 qA = *reinterpret_cast<const ulonglong2*>(sWr + k * CDIM + c0);
            ulonglong2 qB = *reinterpret_cast<const ulonglong2*>(sWr + k * CDIM + c0 + 4);
            u64 n0 = nA.x, n1 = nA.y, n2 = nB.x, n3 = nB.y;
            u64 q0 = qA.x, q1 = qA.y, q2 = qB.x, q3 = qB.y;

            fma2(accT[0][0], a0, n0); fma2(accT[0][1], a0, n1); fma2(accT[0][2], a0, n2); fma2(accT[0][3], a0, n3);
            fma2(accT[1][0], a1, n0); fma2(accT[1][1], a1, n1); fma2(accT[1][2], a1, n2); fma2(accT[1][3], a1, n3);
            fma2(accT[2][0], a2, n0); fma2(accT[2][1], a2, n1); fma2(accT[2][2], a2, n2); fma2(accT[2][3], a2, n3);
            fma2(accT[3][0], a3, n0); fma2(accT[3][1], a3, n1); fma2(accT[3][2], a3, n2); fma2(accT[3][3], a3, n3);

            fma2(accR[0][0], a0, q0); fma2(accR[0][1], a0, q1); fma2(accR[0][2], a0, q2); fma2(accR[0][3], a0, q3);
            fma2(accR[1][0], a1, q0); fma2(accR[1][1], a1, q1); fma2(accR[1][2], a1, q2); fma2(accR[1][3], a1, q3);
            fma2(accR[2][0], a2, q0); fma2(accR[2][1], a2, q1); fma2(accR[2][2], a2, q2); fma2(accR[2][3], a2, q3);
            fma2(accR[3][0], a3, q0); fma2(accR[3][1], a3, q1); fma2(accR[3][2], a3, q2); fma2(accR[3][3], a3, q3);
        }
    }

#pragma unroll
    for (int r = 0; r < 4; r++) {
        const int grow = rowBase + r0 + r;
        if (grow < N) {
            ulonglong2 t0, t1, h0, h1;
            t0.x = accT[r][0]; t0.y = accT[r][1]; t1.x = accT[r][2]; t1.y = accT[r][3];
            h0.x = accR[r][0]; h0.y = accR[r][1]; h1.x = accR[r][2]; h1.y = accR[r][3];
            *reinterpret_cast<ulonglong2*>(T + (size_t)grow * CDIM + c0)     = t0;
            *reinterpret_cast<ulonglong2*>(T + (size_t)grow * CDIM + c0 + 4) = t1;
            *reinterpret_cast<ulonglong2*>(H + (size_t)grow * CDIM + c0)     = h0;
            *reinterpret_cast<ulonglong2*>(H + (size_t)grow * CDIM + c0 + 4) = h1;
        }
    }
}

// ---------------- host-side CSR build helper (on a given stream) ----------------
static void build_csr(const int* src, const int* dst, const float* attr, int E,
                      int* cnt, int* off, int* cur, int2* edges, int* bsum, int nNodes,
                      cudaStream_t s)
{
    const int n1 = nNodes + 1;
    const int nb = (n1 + 1023) / 1024;
    zero_int<<<(n1 + 1023) / 1024, 256, 0, s>>>(cnt, n1);
    hist_kernel<<<(E + 1023) / 1024, 256, 0, s>>>(dst, cnt, E);
    reduce_blk<<<nb, 256, 0, s>>>(cnt, bsum, n1);
    scan_partials<<<1, 512, 0, s>>>(bsum, nb);
    scan_final<<<nb, 256, 0, s>>>(cnt, bsum, off, cur, n1);
    permute_kernel<<<(E + 1023) / 1024, 256, 0, s>>>(src, dst, attr, cur, edges, E);
}

// ---------------- launch ----------------
extern "C" void kernel_launch(void* const* d_in, const int* in_sizes, int n_in,
                              void* d_out, int out_size)
{
    const float* x    = (const float*)d_in[0];
    const float* W1r  = (const float*)d_in[1];
    const float* W1n  = (const float*)d_in[2];
    const float* b1   = (const float*)d_in[3];
    const float* W2r  = (const float*)d_in[4];
    const float* W2n  = (const float*)d_in[5];
    const float* b2   = (const float*)d_in[6];
    const int*   psrc = (const int*)d_in[7];
    const int*   pdst = (const int*)d_in[8];
    const float* patt = (const float*)d_in[9];
    const int*   csrc = (const int*)d_in[10];
    const int*   cdst = (const int*)d_in[11];
    const float* catt = (const float*)d_in[12];
    const int*   usrc = (const int*)d_in[13];
    const int*   udst = (const int*)d_in[14];
    const float* uatt = (const float*)d_in[15];

    const int Ep = in_sizes[7];
    const int Ec = in_sizes[10];
    const int Eu = in_sizes[13];

    float* out = (float*)d_out;

    float *xc, *tb, *hb;
    cudaGetSymbolAddress((void**)&xc, g_xc);
    cudaGetSymbolAddress((void**)&tb, g_t);
    cudaGetSymbolAddress((void**)&hb, g_h);

    int *pcnt, *poff, *pcur, *ccnt, *coff, *ccur, *ucnt, *uoff, *ucur, *bsum;
    int2 *pedg, *cedg, *uedg;
    cudaGetSymbolAddress((void**)&pcnt, g_pool_cnt);
    cudaGetSymbolAddress((void**)&poff, g_pool_off);
    cudaGetSymbolAddress((void**)&pcur, g_pool_cur);
    cudaGetSymbolAddress((void**)&pedg, g_pool_edges);
    cudaGetSymbolAddress((void**)&ccnt, g_conv_cnt);
    cudaGetSymbolAddress((void**)&coff, g_conv_off);
    cudaGetSymbolAddress((void**)&ccur, g_conv_cur);
    cudaGetSymbolAddress((void**)&cedg, g_conv_edges);
    cudaGetSymbolAddress((void**)&ucnt, g_unp_cnt);
    cudaGetSymbolAddress((void**)&uoff, g_unp_off);
    cudaGetSymbolAddress((void**)&ucur, g_unp_cur);
    cudaGetSymbolAddress((void**)&uedg, g_unp_edges);
    cudaGetSymbolAddress((void**)&bsum, g_bsum);

    static cudaStream_t sB = nullptr, sC = nullptr;
    static cudaEvent_t ev0 = nullptr, evB = nullptr, evC = nullptr;
    if (sB == nullptr) {
        cudaStreamCreateWithFlags(&sB, cudaStreamNonBlocking);
        cudaStreamCreateWithFlags(&sC, cudaStreamNonBlocking);
        cudaEventCreateWithFlags(&ev0, cudaEventDisableTiming);
        cudaEventCreateWithFlags(&evB, cudaEventDisableTiming);
        cudaEventCreateWithFlags(&evC, cudaEventDisableTiming);
    }

    // fork: conv CSR on sB, unpool CSR on sC
    cudaEventRecord(ev0, 0);
    cudaStreamWaitEvent(sB, ev0, 0);
    cudaStreamWaitEvent(sC, ev0, 0);
    build_csr(csrc, cdst, catt, Ec, ccnt, coff, ccur, cedg, bsum + 512,  NCC, sB);
    cudaEventRecord(evB, sB);
    build_csr(usrc, udst, uatt, Eu, ucnt, uoff, ucur, uedg, bsum + 1024, NFF, sC);
    cudaEventRecord(evC, sC);

    // critical path
    build_csr(psrc, pdst, patt, Ep, pcnt, poff, pcur, pedg, bsum, NCC, 0);

    const int gthreadsC = NCC * 8;
    const int gthreadsF = NFF * 8;

    gather_kernel<false><<<(gthreadsC + 255) / 256, 256>>>(x, pedg, poff, xc, NCC);

    dual_gemm<<<(NCC + ROWS_PER_BLK - 1) / ROWS_PER_BLK, 256>>>(xc, W1n, W1r, b1, tb, hb, NCC);
    cudaStreamWaitEvent(0, evB, 0);
    gather_kernel<true><<<(gthreadsC + 255) / 256, 256>>>(tb, cedg, coff, hb, NCC);

    dual_gemm<<<(NCC + ROWS_PER_BLK - 1) / ROWS_PER_BLK, 256>>>(hb, W2n, W2r, b2, tb, xc, NCC);
    gather_kernel<true><<<(gthreadsC + 255) / 256, 256>>>(tb, cedg, coff, xc, NCC);

    cudaStreamWaitEvent(0, evC, 0);
    gather_kernel<false><<<(gthreadsF + 255) / 256, 256>>>(xc, uedg, uoff, out, NFF);
}